// round 14
// baseline (speedup 1.0000x reference)
#include <cuda_runtime.h>
#include <math.h>
#include <stdint.h>

#define BATCH   32
#define SEQ     512
#define NHEADS  8
#define HID     64
#define INDIM   256
#define HDIM    512
#define MTOK    (BATCH*SEQ)       /* 16384 tokens */

// ---------------- scratch buffers (device globals; no allocation) ----------
__device__ float g_qkv  [(size_t)MTOK * 3 * HDIM];
__device__ float g_upd  [(size_t)MTOK * HDIM];
__device__ float g_featr[(size_t)MTOK * INDIM];
__device__ float g_wcat [(size_t)INDIM * 3 * HDIM];

// ---------------- small helpers ----------------
__device__ __forceinline__ float totf32(float x) {
    uint32_t u;
    asm("cvt.rna.tf32.f32 %0, %1;" : "=r"(u) : "f"(x));
    return __uint_as_float(u);
}
__device__ __forceinline__ float4 cvt4(float4 v) {
    return make_float4(totf32(v.x), totf32(v.y), totf32(v.z), totf32(v.w));
}
__device__ __forceinline__ float fsqrt_fast(float x) {
    float y;
    asm("sqrt.approx.f32 %0, %1;" : "=f"(y) : "f"(x));
    return y;
}
// exp2 on the FMA pipe; |rel err| ~2e-6 (below subsequent tf32 rounding)
__device__ __forceinline__ float exp2_fast(float x) {
    x = fminf(fmaxf(x, -120.f), 120.f);
    float z = x + 12582912.0f;
    float n = z - 12582912.0f;
    float r = x - n;
    int   ni = __float_as_int(z) - 0x4B400000;
    float s = __int_as_float((ni + 127) << 23);
    float p = 1.3333558e-3f;
    p = fmaf(p, r, 9.6181291e-3f);
    p = fmaf(p, r, 5.5504110e-2f);
    p = fmaf(p, r, 2.4022651e-1f);
    p = fmaf(p, r, 6.9314718e-1f);
    p = fmaf(p, r, 1.0f);
    return p * s;
}
__device__ __forceinline__ void mma8(float c[4], const float a[4], const float b[2]) {
    asm volatile(
        "mma.sync.aligned.m16n8k8.row.col.f32.tf32.tf32.f32 "
        "{%0,%1,%2,%3}, {%4,%5,%6,%7}, {%8,%9}, {%0,%1,%2,%3};\n"
        : "+f"(c[0]), "+f"(c[1]), "+f"(c[2]), "+f"(c[3])
        : "r"(__float_as_uint(a[0])), "r"(__float_as_uint(a[1])),
          "r"(__float_as_uint(a[2])), "r"(__float_as_uint(a[3])),
          "r"(__float_as_uint(b[0])), "r"(__float_as_uint(b[1])));
}
__device__ __forceinline__ void cp16(float* dst_smem, const float* src) {
    uint32_t d = (uint32_t)__cvta_generic_to_shared(dst_smem);
    asm volatile("cp.async.cg.shared.global [%0], [%1], 16;" :: "r"(d), "l"(src));
}
__device__ __forceinline__ void cp4(float* dst_smem, const float* src) {
    uint32_t d = (uint32_t)__cvta_generic_to_shared(dst_smem);
    asm volatile("cp.async.ca.shared.global [%0], [%1], 4;" :: "r"(d), "l"(src));
}
#define CP_COMMIT()  asm volatile("cp.async.commit_group;")
#define CP_WAIT0()   asm volatile("cp.async.wait_group 0;")
#define CP_WAIT1()   asm volatile("cp.async.wait_group 1;")

// ------------- prep: tf32-round feat; concat+round Wq|Wk|Wv ----------------
__global__ __launch_bounds__(256)
void prep_round(const float* __restrict__ feat, const float* __restrict__ Wq,
                const float* __restrict__ Wk, const float* __restrict__ Wv,
                float* __restrict__ featr, float* __restrict__ wcat) {
    const int NF4 = MTOK * INDIM / 4;
    int idx = blockIdx.x * 256 + threadIdx.x;
    if (idx < NF4) {
        ((float4*)featr)[idx] = cvt4(((const float4*)feat)[idx]);
    } else {
        int j = idx - NF4;
        int k  = j / 384;
        int c4 = (j % 384) * 4;
        const float* src = (c4 < 512)  ? &Wq[k*512 + c4] :
                           (c4 < 1024) ? &Wk[k*512 + c4 - 512] :
                                         &Wv[k*512 + c4 - 1024];
        ((float4*)wcat)[j] = cvt4(*(const float4*)src);
    }
}

// ------ QKV GEMM v2: BM=128 BN=128 BK=32, 8 warps (2x4), warp tile 64x32 ---
#define GAS 36
#define GBS 136
#define GA_BUF (128*GAS)
#define GB_BUF (32*GBS)
#define GEMM_FLOATS (2*(GA_BUF+GB_BUF))

__global__ __launch_bounds__(256, 2)
void qkv_gemm2(const float* __restrict__ A, const float* __restrict__ B,
               float* __restrict__ C) {
    extern __shared__ float smg[];
    float* As = smg;
    float* Bs = smg + 2*GA_BUF;
    const int t = threadIdx.x;
    const int w = t >> 5, l = t & 31, g = l >> 2, ti = l & 3;
    const int wrow = (w >> 2) * 64;
    const int wcol = (w & 3) * 32;
    const int bm = blockIdx.y * 128, bn = blockIdx.x * 128;

    {   // prologue chunk 0
        #pragma unroll
        for (int j = 0; j < 4; j++) {
            int i = t + 256*j; int r = i >> 3, c4 = (i & 7) * 4;
            cp16(&As[r*GAS + c4], &A[(size_t)(bm + r)*INDIM + c4]);
        }
        #pragma unroll
        for (int j = 0; j < 4; j++) {
            int i = t + 256*j; int r = i >> 5, c4 = (i & 31) * 4;
            cp16(&Bs[r*GBS + c4], &B[(size_t)r*1536 + bn + c4]);
        }
        CP_COMMIT();
    }

    float acc[4][4][4] = {};
    for (int kt = 0; kt < INDIM; kt += 32) {
        CP_WAIT0();
        __syncthreads();
        const int buf = (kt >> 5) & 1;
        if (kt + 32 < INDIM) {
            float* Ad = As + (buf ^ 1) * GA_BUF;
            float* Bd = Bs + (buf ^ 1) * GB_BUF;
            #pragma unroll
            for (int j = 0; j < 4; j++) {
                int i = t + 256*j; int r = i >> 3, c4 = (i & 7) * 4;
                cp16(&Ad[r*GAS + c4], &A[(size_t)(bm + r)*INDIM + kt + 32 + c4]);
            }
            #pragma unroll
            for (int j = 0; j < 4; j++) {
                int i = t + 256*j; int r = i >> 5, c4 = (i & 31) * 4;
                cp16(&Bd[r*GBS + c4], &B[(size_t)(kt + 32 + r)*1536 + bn + c4]);
            }
            CP_COMMIT();
        }
        const float* Af = As + buf * GA_BUF;
        const float* Bf = Bs + buf * GB_BUF;
        #pragma unroll
        for (int ks = 0; ks < 4; ks++) {
            float a[4][4], bfr[4][2];
            #pragma unroll
            for (int mt = 0; mt < 4; mt++) {
                int r = wrow + mt*16;
                a[mt][0] = Af[(r + g)     * GAS + ks*8 + ti];
                a[mt][1] = Af[(r + g + 8) * GAS + ks*8 + ti];
                a[mt][2] = Af[(r + g)     * GAS + ks*8 + ti + 4];
                a[mt][3] = Af[(r + g + 8) * GAS + ks*8 + ti + 4];
            }
            #pragma unroll
            for (int nt = 0; nt < 4; nt++) {
                int cc = wcol + nt*8 + g;
                bfr[nt][0] = Bf[(ks*8 + ti)     * GBS + cc];
                bfr[nt][1] = Bf[(ks*8 + ti + 4) * GBS + cc];
            }
            #pragma unroll
            for (int mt = 0; mt < 4; mt++)
                #pragma unroll
                for (int nt = 0; nt < 4; nt++)
                    mma8(acc[mt][nt], a[mt], bfr[nt]);
        }
    }
    #pragma unroll
    for (int mt = 0; mt < 4; mt++)
        #pragma unroll
        for (int nt = 0; nt < 4; nt++) {
            int row = bm + wrow + mt*16 + g;
            int col = bn + wcol + nt*8 + 2*ti;
            *(float2*)&C[(size_t)row*1536 + col] =
                make_float2(totf32(acc[mt][nt][0]), totf32(acc[mt][nt][1]));
            *(float2*)&C[(size_t)(row+8)*1536 + col] =
                make_float2(totf32(acc[mt][nt][2]), totf32(acc[mt][nt][3]));
        }
}

// ---------------- flash attention (dist recomputed in-register) ------------
#define QSS 68
#define PSS 68
#define KSS 68
#define VSS 72
#define AOFS_P  (64*QSS)
#define AOFS_K  (AOFS_P + 64*PSS)
#define AOFS_V  (AOFS_K + 2*64*KSS)
#define AOFS_PQ (AOFS_V + 2*64*VSS)
#define AOFS_PK (AOFS_PQ + 192)
#define AOFS_RS (AOFS_PK + 384)
#define AOFS_RT (AOFS_RS + 256)
#define ATT_FLOATS (AOFS_RT + 64)

__global__ __launch_bounds__(512, 2)
void attn_kernel(const float* __restrict__ pos, const float* __restrict__ qkv,
                 float* __restrict__ upd) {
    extern __shared__ float sm[];
    float* Qs  = sm;
    float* P   = sm + AOFS_P;
    float* Kb  = sm + AOFS_K;
    float* Vb  = sm + AOFS_V;
    float* pq  = sm + AOFS_PQ;
    float* pk  = sm + AOFS_PK;
    float* rsP = sm + AOFS_RS;
    float* rsum= sm + AOFS_RT;

    const int t = threadIdx.x;
    const int w = t >> 5, l = t & 31, g = l >> 2, ti = l & 3;
    const int wm = w >> 2, wn = w & 3;
    const int qt = blockIdx.x, h = blockIdx.y, b = blockIdx.z;
    const int q0g = qt * 64, tokbase = b * SEQ;

    #pragma unroll
    for (int i = t; i < 64 * 16; i += 512) {
        int q = i >> 4, d4 = (i & 15) * 4;
        cp16(&Qs[q*QSS + d4], &qkv[(size_t)(tokbase + q0g + q)*1536 + h*64 + d4]);
    }
    #pragma unroll
    for (int i = t; i < 64 * 16; i += 512) {
        int k = i >> 4, d4 = (i & 15) * 4;
        cp16(&Kb[k*KSS + d4], &qkv[(size_t)(tokbase + k)*1536 + 512 + h*64 + d4]);
    }
    #pragma unroll
    for (int i = t; i < 64 * 16; i += 512) {
        int k = i >> 4, d4 = (i & 15) * 4;
        cp16(&Vb[k*VSS + d4], &qkv[(size_t)(tokbase + k)*1536 + 1024 + h*64 + d4]);
    }
    if (t < 192) cp4(&pq[t], &pos[(size_t)(tokbase + q0g)*3 + t]);
    else if (t < 384) cp4(&pk[t-192], &pos[(size_t)tokbase*3 + (t-192)]);
    CP_COMMIT();

    const float K1 = (float)(1.4426950408889634 * 0.08838834764831845);
    const float C2 = (float)(1.4142135623730951 * 1.4426950408889634);
    float cO[2][4] = {};
    float rs0 = 0.f, rs1 = 0.f;

    for (int c = 0; c < 8; c++) {
        CP_WAIT0();
        __syncthreads();
        if (c < 7) {
            const int nx = (c + 1) & 1;
            #pragma unroll
            for (int i = t; i < 64 * 16; i += 512) {
                int k = i >> 4, d4 = (i & 15) * 4;
                cp16(&Kb[nx*64*KSS + k*KSS + d4],
                     &qkv[(size_t)(tokbase + (c+1)*64 + k)*1536 + 512 + h*64 + d4]);
            }
            #pragma unroll
            for (int i = t; i < 64 * 16; i += 512) {
                int k = i >> 4, d4 = (i & 15) * 4;
                cp16(&Vb[nx*64*VSS + k*VSS + d4],
                     &qkv[(size_t)(tokbase + (c+1)*64 + k)*1536 + 1024 + h*64 + d4]);
            }
            if (t < 192) cp4(&pk[nx*192 + t], &pos[(size_t)(tokbase + (c+1)*64)*3 + t]);
            CP_COMMIT();
        }
        const float* Kc = Kb + (c & 1) * 64 * KSS;

        float cS[2][4] = {};
        #pragma unroll
        for (int ks = 0; ks < 8; ks++) {
            float a[4], bf[2][2];
            a[0] = Qs[(wm*16 + g)     * QSS + ks*8 + ti];
            a[1] = Qs[(wm*16 + g + 8) * QSS + ks*8 + ti];
            a[2] = Qs[(wm*16 + g)     * QSS + ks*8 + ti + 4];
            a[3] = Qs[(wm*16 + g + 8) * QSS + ks*8 + ti + 4];
            #pragma unroll
            for (int nt = 0; nt < 2; nt++) {
                int key = wn*16 + nt*8 + g;
                bf[nt][0] = Kc[key*KSS + ks*8 + ti];
                bf[nt][1] = Kc[key*KSS + ks*8 + ti + 4];
            }
            mma8(cS[0], a, bf[0]);
            mma8(cS[1], a, bf[1]);
        }

        {
            const int r0 = wm*16 + g;
            float qx0 = pq[r0*3],     qy0 = pq[r0*3+1],     qz0 = pq[r0*3+2];
            float qx1 = pq[(r0+8)*3], qy1 = pq[(r0+8)*3+1], qz1 = pq[(r0+8)*3+2];
            const float* pkc = pk + (c & 1) * 192;
            #pragma unroll
            for (int nt = 0; nt < 2; nt++) {
                int kl = wn*16 + nt*8 + 2*ti;
                float kx0 = pkc[kl*3],   ky0 = pkc[kl*3+1], kz0 = pkc[kl*3+2];
                float kx1 = pkc[kl*3+3], ky1 = pkc[kl*3+4], kz1 = pkc[kl*3+5];
                float dx, dy, dz;
                dx = qx0-kx0; dy = qy0-ky0; dz = qz0-kz0;
                float e00 = fsqrt_fast(fmaf(dx,dx,fmaf(dy,dy,dz*dz))) * C2;
                dx = qx0-kx1; dy = qy0-ky1; dz = qz0-kz1;
                float e01 = fsqrt_fast(fmaf(dx,dx,fmaf(dy,dy,dz*dz))) * C2;
                dx = qx1-kx0; dy = qy1-ky0; dz = qz1-kz0;
                float e10 = fsqrt_fast(fmaf(dx,dx,fmaf(dy,dy,dz*dz))) * C2;
                dx = qx1-kx1; dy = qy1-ky1; dz = qz1-kz1;
                float e11 = fsqrt_fast(fmaf(dx,dx,fmaf(dy,dy,dz*dz))) * C2;
                float2 u0, u1;
                u0.x = totf32(exp2_fast(fmaf(cS[nt][0], K1, e00)));
                u0.y = totf32(exp2_fast(fmaf(cS[nt][1], K1, e01)));
                u1.x = totf32(exp2_fast(fmaf(cS[nt][2], K1, e10)));
                u1.y = totf32(exp2_fast(fmaf(cS[nt][3], K1, e11)));
                *(float2*)&P[r0*PSS + kl]     = u0;
                *(float2*)&P[(r0+8)*PSS + kl] = u1;
                rs0 += u0.x + u0.y;
                rs1 += u1.x + u1.y;
            }
        }
        __syncthreads();

        const float* Vc = Vb + (c & 1) * 64 * VSS;
        #pragma unroll
        for (int ks = 0; ks < 8; ks++) {
            float a[4], bf[2][2];
            a[0] = P[(wm*16 + g)     * PSS + ks*8 + ti];
            a[1] = P[(wm*16 + g + 8) * PSS + ks*8 + ti];
            a[2] = P[(wm*16 + g)     * PSS + ks*8 + ti + 4];
            a[3] = P[(wm*16 + g + 8) * PSS + ks*8 + ti + 4];
            #pragma unroll
            for (int nt = 0; nt < 2; nt++) {
                int dc = wn*16 + nt*8 + g;
                bf[nt][0] = Vc[(ks*8 + ti)     * VSS + dc];
                bf[nt][1] = Vc[(ks*8 + ti + 4) * VSS + dc];
            }
            mma8(cO[0], a, bf[0]);
            mma8(cO[1], a, bf[1]);
        }
    }

    rs0 += __shfl_xor_sync(0xffffffffu, rs0, 1);
    rs0 += __shfl_xor_sync(0xffffffffu, rs0, 2);
    rs1 += __shfl_xor_sync(0xffffffffu, rs1, 1);
    rs1 += __shfl_xor_sync(0xffffffffu, rs1, 2);
    __syncthreads();
    if (ti == 0) {
        rsP[wn*64 + wm*16 + g]     = rs0;
        rsP[wn*64 + wm*16 + g + 8] = rs1;
    }
    __syncthreads();
    if (t < 64) rsum[t] = 1.f / (rsP[t] + rsP[64 + t] + rsP[128 + t] + rsP[192 + t]);
    __syncthreads();

    {
        float inv0 = rsum[wm*16 + g];
        float inv1 = rsum[wm*16 + g + 8];
        #pragma unroll
        for (int nt = 0; nt < 2; nt++) {
            int r = tokbase + q0g + wm*16 + g;
            int col = h*64 + wn*16 + nt*8 + 2*ti;
            *(float2*)&upd[(size_t)r * HDIM + col] =
                make_float2(totf32(cO[nt][0]*inv0), totf32(cO[nt][1]*inv0));
            *(float2*)&upd[(size_t)(r + 8) * HDIM + col] =
                make_float2(totf32(cO[nt][2]*inv1), totf32(cO[nt][3]*inv1));
        }
    }
}

// ------- fused 3-layer MLP v2: 256 blocks x 64 rows, W2/W3 from L1 ---------
#define NH1S 132
#define NH2S 68
#define NAS  36
#define NBS  136
#define NOFS_H2 (64*NH1S)              // 8448
#define NOFS_AS (NOFS_H2 + 64*NH2S)    // 12800
#define NOFS_BS (NOFS_AS + 64*NAS)     // 15104
#define MLP2_FLOATS (NOFS_BS + 32*NBS) // 19456 floats = 77824 B

__global__ __launch_bounds__(512, 2)
void mlp_fused2(const float* __restrict__ X,
                const float* __restrict__ W1, const float* __restrict__ b1,
                const float* __restrict__ W2, const float* __restrict__ b2,
                const float* __restrict__ W3, const float* __restrict__ b3,
                float* __restrict__ out) {
    extern __shared__ float sm[];
    float* H1 = sm;                  // [64][132]
    float* H2 = sm + NOFS_H2;        // [64][68]
    float* As = sm + NOFS_AS;        // [64][36]
    float* Bs = sm + NOFS_BS;        // [32][136]

    const int t = threadIdx.x;
    const int w = t >> 5, l = t & 31, g = l >> 2, ti = l & 3;
    const int wm = w >> 2, wn = w & 3;     // 4x4 warp grid
    const int bm = blockIdx.x * 64;

    // ---- phase 1: H1 = silu(X @ W1 + b1), K=512, reg-prefetch pipeline ----
    const float* A = X + (size_t)bm * HDIM;
    float4 ra;                       // 64*8 float4 = 512 -> 1 per thread
    float4 rb[2];                    // 32*32 float4 = 1024 -> 2 per thread
    ra = *(const float4*)&A[(size_t)(t >> 3) * HDIM + (t & 7) * 4];
    #pragma unroll
    for (int j = 0; j < 2; j++) { int i = t + 512*j;
        rb[j] = *(const float4*)&W1[(size_t)(i >> 5) * 128 + (i & 31) * 4]; }

    float c1[4][4] = {};
    for (int kt = 0; kt < HDIM; kt += 32) {
        *(float4*)&As[(t >> 3)*NAS + (t & 7)*4] = ra;      // X already tf32
        #pragma unroll
        for (int j = 0; j < 2; j++) { int i = t + 512*j;
            *(float4*)&Bs[(i >> 5)*NBS + (i & 31)*4] = cvt4(rb[j]); }
        __syncthreads();
        if (kt + 32 < HDIM) {
            ra = *(const float4*)&A[(size_t)(t >> 3) * HDIM + kt + 32 + (t & 7)*4];
            #pragma unroll
            for (int j = 0; j < 2; j++) { int i = t + 512*j;
                rb[j] = *(const float4*)&W1[(size_t)(kt + 32 + (i >> 5)) * 128 + (i & 31)*4]; }
        }
        #pragma unroll
        for (int ks = 0; ks < 4; ks++) {
            float a[4], bfr[4][2];
            int r = wm * 16;
            a[0] = As[(r + g)     * NAS + ks*8 + ti];
            a[1] = As[(r + g + 8) * NAS + ks*8 + ti];
            a[2] = As[(r + g)     * NAS + ks*8 + ti + 4];
            a[3] = As[(r + g + 8) * NAS + ks*8 + ti + 4];
            #pragma unroll
            for (int nt = 0; nt < 4; nt++) {
                int cc = wn*32 + nt*8 + g;
                bfr[nt][0] = Bs[(ks*8 + ti)     * NBS + cc];
                bfr[nt][1] = Bs[(ks*8 + ti + 4) * NBS + cc];
            }
            #pragma unroll
            for (int nt = 0; nt < 4; nt++)
                mma8(c1[nt], a, bfr[nt]);
        }
        __syncthreads();
    }
    #pragma unroll
    for (int nt = 0; nt < 4; nt++) {
        int row = wm*16 + g;
        int col = wn*32 + nt*8 + 2*ti;
        float bb0 = b1[col], bb1 = b1[col+1];
        float v0 = c1[nt][0] + bb0, v1 = c1[nt][1] + bb1;
        float v2 = c1[nt][2] + bb0, v3 = c1[nt][3] + bb1;
        v0 = totf32(v0 / (1.f + __expf(-v0))); v1 = totf32(v1 / (1.f + __expf(-v1)));
        v2 = totf32(v2 / (1.f + __expf(-v2))); v3 = totf32(v3 / (1.f + __expf(-v3)));
        *(float2*)&H1[row*NH1S + col]     = make_float2(v0, v1);
        *(float2*)&H1[(row+8)*NH1S + col] = make_float2(v2, v3);
    }
    __syncthreads();

    // ---- phase 2: H2 = silu(H1 @ W2 + b2), K=128; W2 from gmem/L1 ----
    float c2[2][4] = {};
    #pragma unroll
    for (int ks = 0; ks < 16; ks++) {
        float a[4], bfr[2][2];
        int r = wm * 16;
        a[0] = H1[(r + g)     * NH1S + ks*8 + ti];
        a[1] = H1[(r + g + 8) * NH1S + ks*8 + ti];
        a[2] = H1[(r + g)     * NH1S + ks*8 + ti + 4];
        a[3] = H1[(r + g + 8) * NH1S + ks*8 + ti + 4];
        #pragma unroll
        for (int nt = 0; nt < 2; nt++) {
            int cc = wn*16 + nt*8 + g;
            bfr[nt][0] = totf32(W2[(ks*8 + ti)     * 64 + cc]);
            bfr[nt][1] = totf32(W2[(ks*8 + ti + 4) * 64 + cc]);
        }
        mma8(c2[0], a, bfr[0]);
        mma8(c2[1], a, bfr[1]);
    }
    #pragma unroll
    for (int nt = 0; nt < 2; nt++) {
        int row = wm*16 + g;
        int col = wn*16 + nt*8 + 2*ti;
        float bb0 = b2[col], bb1 = b2[col+1];
        float v0 = c2[nt][0] + bb0, v1 = c2[nt][1] + bb1;
        float v2 = c2[nt][2] + bb0, v3 = c2[nt][3] + bb1;
        v0 = totf32(v0 / (1.f + __expf(-v0))); v1 = totf32(v1 / (1.f + __expf(-v1)));
        v2 = totf32(v2 / (1.f + __expf(-v2))); v3 = totf32(v3 / (1.f + __expf(-v3)));
        *(float2*)&H2[row*NH2S + col]     = make_float2(v0, v1);
        *(float2*)&H2[(row+8)*NH2S + col] = make_float2(v2, v3);
    }
    __syncthreads();

    // ---- phase 3: out = silu(H2 @ W3 + b3), K=64, N=256; W3 from gmem/L1 ----
    float c3[8][4] = {};
    #pragma unroll
    for (int ks = 0; ks < 8; ks++) {
        float a[4];
        int r = wm * 16;
        a[0] = H2[(r + g)     * NH2S + ks*8 + ti];
        a[1] = H2[(r + g + 8) * NH2S + ks*8 + ti];
        a[2] = H2[(r + g)     * NH2S + ks*8 + ti + 4];
        a[3] = H2[(r + g + 8) * NH2S + ks*8 + ti + 4];
        #pragma unroll
        for (int nt = 0; nt < 8; nt++) {
            float bfr[2];
            int cc = wn*64 + nt*8 + g;
            bfr[0] = totf32(W3[(ks*8 + ti)     * 256 + cc]);
            bfr[1] = totf32(W3[(ks*8 + ti + 4) * 256 + cc]);
            mma8(c3[nt], a, bfr);
        }
    }
    #pragma unroll
    for (int nt = 0; nt < 8; nt++) {
        int row = bm + wm*16 + g;
        int col = wn*64 + nt*8 + 2*ti;
        float bb0 = b3[col], bb1 = b3[col+1];
        float v0 = c3[nt][0] + bb0, v1 = c3[nt][1] + bb1;
        float v2 = c3[nt][2] + bb0, v3 = c3[nt][3] + bb1;
        v0 = v0 / (1.f + __expf(-v0)); v1 = v1 / (1.f + __expf(-v1));
        v2 = v2 / (1.f + __expf(-v2)); v3 = v3 / (1.f + __expf(-v3));
        *(float2*)&out[(size_t)row * INDIM + col]     = make_float2(v0, v1);
        *(float2*)&out[(size_t)(row+8) * INDIM + col] = make_float2(v2, v3);
    }
}

// ---------------- launch ----------------
extern "C" void kernel_launch(void* const* d_in, const int* in_sizes, int n_in,
                              void* d_out, int out_size) {
    const float* pos  = (const float*)d_in[0];
    const float* feat = (const float*)d_in[1];
    const float* Wk   = (const float*)d_in[2];
    const float* Wq   = (const float*)d_in[3];
    const float* Wv   = (const float*)d_in[4];
    const float* W1   = (const float*)d_in[5];
    const float* b1   = (const float*)d_in[6];
    const float* W2   = (const float*)d_in[7];
    const float* b2   = (const float*)d_in[8];
    const float* W3   = (const float*)d_in[9];
    const float* b3   = (const float*)d_in[10];
    float* out = (float*)d_out;

    void* p;
    cudaGetSymbolAddress(&p, g_qkv);   float* qkv   = (float*)p;
    cudaGetSymbolAddress(&p, g_upd);   float* upd   = (float*)p;
    cudaGetSymbolAddress(&p, g_featr); float* featr = (float*)p;
    cudaGetSymbolAddress(&p, g_wcat);  float* wcat  = (float*)p;

    prep_round<<<(MTOK*INDIM/4 + INDIM*1536/4 + 255)/256, 256>>>(feat, Wq, Wk, Wv, featr, wcat);

    size_t gsh = (size_t)GEMM_FLOATS * sizeof(float);
    cudaFuncSetAttribute(qkv_gemm2, cudaFuncAttributeMaxDynamicSharedMemorySize, (int)gsh);
    qkv_gemm2<<<dim3(12, MTOK/128), 256, gsh>>>(featr, wcat, qkv);

    size_t ash = (size_t)ATT_FLOATS * sizeof(float);
    cudaFuncSetAttribute(attn_kernel, cudaFuncAttributeMaxDynamicSharedMemorySize, (int)ash);
    attn_kernel<<<dim3(SEQ/64, NHEADS, BATCH), 512, ash>>>(pos, qkv, upd);

    size_t msh = (size_t)MLP2_FLOATS * sizeof(float);
    cudaFuncSetAttribute(mlp_fused2, cudaFuncAttributeMaxDynamicSharedMemorySize, (int)msh);
    mlp_fused2<<<MTOK/64, 512, msh>>>(upd, W1, b1, W2, b2, W3, b3, out);
}

// round 16
// speedup vs baseline: 1.0397x; 1.0397x over previous
// KeypointMHA — r16 resubmission of r15 source (hash-perturbed to force clean
// broker build; semantics identical to the r13-proven kernel + exp2 declamp).
#include <cuda_runtime.h>
#include <math.h>
#include <stdint.h>

#define BATCH   32
#define SEQ     512
#define NHEADS  8
#define HID     64
#define INDIM   256
#define HDIM    512
#define MTOK    (BATCH*SEQ)

// ---- scratch (device globals; allocation-free contract) ----
__device__ float g_qkv  [(size_t)MTOK * 3 * HDIM];
__device__ float g_upd  [(size_t)MTOK * HDIM];
__device__ float g_featr[(size_t)MTOK * INDIM];
__device__ float g_wcat [(size_t)INDIM * 3 * HDIM];

// ---- helpers ----
__device__ __forceinline__ float totf32(float x) {
    uint32_t u;
    asm("cvt.rna.tf32.f32 %0, %1;" : "=r"(u) : "f"(x));
    return __uint_as_float(u);
}
__device__ __forceinline__ float4 cvt4(float4 v) {
    return make_float4(totf32(v.x), totf32(v.y), totf32(v.z), totf32(v.w));
}
__device__ __forceinline__ float fsqrt_fast(float x) {
    float y;
    asm("sqrt.approx.f32 %0, %1;" : "=f"(y) : "f"(x));
    return y;
}
// exp2 on the FMA pipe; no range clamp (attention scores bounded by construction)
__device__ __forceinline__ float exp2_fast(float x) {
    float z = x + 12582912.0f;
    float n = z - 12582912.0f;
    float r = x - n;
    int   ni = __float_as_int(z) - 0x4B400000;
    float s = __int_as_float((ni + 127) << 23);
    float p = 1.3333558e-3f;
    p = fmaf(p, r, 9.6181291e-3f);
    p = fmaf(p, r, 5.5504110e-2f);
    p = fmaf(p, r, 2.4022651e-1f);
    p = fmaf(p, r, 6.9314718e-1f);
    p = fmaf(p, r, 1.0f);
    return p * s;
}
__device__ __forceinline__ void mma8(float c[4], const float a[4], const float b[2]) {
    asm volatile(
        "mma.sync.aligned.m16n8k8.row.col.f32.tf32.tf32.f32 "
        "{%0,%1,%2,%3}, {%4,%5,%6,%7}, {%8,%9}, {%0,%1,%2,%3};\n"
        : "+f"(c[0]), "+f"(c[1]), "+f"(c[2]), "+f"(c[3])
        : "r"(__float_as_uint(a[0])), "r"(__float_as_uint(a[1])),
          "r"(__float_as_uint(a[2])), "r"(__float_as_uint(a[3])),
          "r"(__float_as_uint(b[0])), "r"(__float_as_uint(b[1])));
}
__device__ __forceinline__ void cp16(float* dst_smem, const float* src) {
    uint32_t d = (uint32_t)__cvta_generic_to_shared(dst_smem);
    asm volatile("cp.async.cg.shared.global [%0], [%1], 16;" :: "r"(d), "l"(src));
}
__device__ __forceinline__ void cp4(float* dst_smem, const float* src) {
    uint32_t d = (uint32_t)__cvta_generic_to_shared(dst_smem);
    asm volatile("cp.async.ca.shared.global [%0], [%1], 4;" :: "r"(d), "l"(src));
}
#define CP_COMMIT()  asm volatile("cp.async.commit_group;")
#define CP_WAIT0()   asm volatile("cp.async.wait_group 0;")
#define CP_WAIT1()   asm volatile("cp.async.wait_group 1;")

// ---- prep kernel: tf32-round feat; concat + round Wq|Wk|Wv ----
__global__ __launch_bounds__(256)
void prep_round(const float* __restrict__ feat, const float* __restrict__ Wq,
                const float* __restrict__ Wk, const float* __restrict__ Wv,
                float* __restrict__ featr, float* __restrict__ wcat) {
    const int NF4 = MTOK * INDIM / 4;
    int idx = blockIdx.x * 256 + threadIdx.x;
    if (idx < NF4) {
        ((float4*)featr)[idx] = cvt4(((const float4*)feat)[idx]);
    } else {
        int j = idx - NF4;
        int row = j / 384;
        int c4  = (j % 384) * 4;
        const float* src = (c4 < 512)  ? &Wq[row*512 + c4] :
                           (c4 < 1024) ? &Wk[row*512 + c4 - 512] :
                                         &Wv[row*512 + c4 - 1024];
        ((float4*)wcat)[j] = cvt4(*(const float4*)src);
    }
}

// ---- QKV GEMM: BM=128 BN=128 BK=32, 8 warps as 2x4, warp tile 64x32 ----
#define GAS 36
#define GBS 136
#define GA_BUF (128*GAS)
#define GB_BUF (32*GBS)
#define GEMM_FLOATS (2*(GA_BUF+GB_BUF))

__global__ __launch_bounds__(256, 2)
void qkv_gemm2(const float* __restrict__ A, const float* __restrict__ B,
               float* __restrict__ C) {
    extern __shared__ float smg[];
    float* As = smg;
    float* Bs = smg + 2*GA_BUF;
    const int t = threadIdx.x;
    const int w = t >> 5, l = t & 31, g = l >> 2, ti = l & 3;
    const int wrow = (w >> 2) * 64;
    const int wcol = (w & 3) * 32;
    const int bm = blockIdx.y * 128, bn = blockIdx.x * 128;

    {
        #pragma unroll
        for (int j = 0; j < 4; j++) {
            int i = t + 256*j; int r = i >> 3, c4 = (i & 7) * 4;
            cp16(&As[r*GAS + c4], &A[(size_t)(bm + r)*INDIM + c4]);
        }
        #pragma unroll
        for (int j = 0; j < 4; j++) {
            int i = t + 256*j; int r = i >> 5, c4 = (i & 31) * 4;
            cp16(&Bs[r*GBS + c4], &B[(size_t)r*1536 + bn + c4]);
        }
        CP_COMMIT();
    }

    float acc[4][4][4] = {};
    for (int kt = 0; kt < INDIM; kt += 32) {
        CP_WAIT0();
        __syncthreads();
        const int buf = (kt >> 5) & 1;
        if (kt + 32 < INDIM) {
            float* Ad = As + (buf ^ 1) * GA_BUF;
            float* Bd = Bs + (buf ^ 1) * GB_BUF;
            #pragma unroll
            for (int j = 0; j < 4; j++) {
                int i = t + 256*j; int r = i >> 3, c4 = (i & 7) * 4;
                cp16(&Ad[r*GAS + c4], &A[(size_t)(bm + r)*INDIM + kt + 32 + c4]);
            }
            #pragma unroll
            for (int j = 0; j < 4; j++) {
                int i = t + 256*j; int r = i >> 5, c4 = (i & 31) * 4;
                cp16(&Bd[r*GBS + c4], &B[(size_t)(kt + 32 + r)*1536 + bn + c4]);
            }
            CP_COMMIT();
        }
        const float* Af = As + buf * GA_BUF;
        const float* Bf = Bs + buf * GB_BUF;
        #pragma unroll
        for (int ks = 0; ks < 4; ks++) {
            float a[4][4], bfr[4][2];
            #pragma unroll
            for (int mt = 0; mt < 4; mt++) {
                int r = wrow + mt*16;
                a[mt][0] = Af[(r + g)     * GAS + ks*8 + ti];
                a[mt][1] = Af[(r + g + 8) * GAS + ks*8 + ti];
                a[mt][2] = Af[(r + g)     * GAS + ks*8 + ti + 4];
                a[mt][3] = Af[(r + g + 8) * GAS + ks*8 + ti + 4];
            }
            #pragma unroll
            for (int nt = 0; nt < 4; nt++) {
                int cc = wcol + nt*8 + g;
                bfr[nt][0] = Bf[(ks*8 + ti)     * GBS + cc];
                bfr[nt][1] = Bf[(ks*8 + ti + 4) * GBS + cc];
            }
            #pragma unroll
            for (int mt = 0; mt < 4; mt++)
                #pragma unroll
                for (int nt = 0; nt < 4; nt++)
                    mma8(acc[mt][nt], a[mt], bfr[nt]);
        }
    }
    #pragma unroll
    for (int mt = 0; mt < 4; mt++)
        #pragma unroll
        for (int nt = 0; nt < 4; nt++) {
            int row = bm + wrow + mt*16 + g;
            int col = bn + wcol + nt*8 + 2*ti;
            *(float2*)&C[(size_t)row*1536 + col] =
                make_float2(totf32(acc[mt][nt][0]), totf32(acc[mt][nt][1]));
            *(float2*)&C[(size_t)(row+8)*1536 + col] =
                make_float2(totf32(acc[mt][nt][2]), totf32(acc[mt][nt][3]));
        }
}

// ---- flash attention (distance recomputed in-register) ----
#define QSS 68
#define PSS 68
#define KSS 68
#define VSS 72
#define AOFS_P  (64*QSS)
#define AOFS_K  (AOFS_P + 64*PSS)
#define AOFS_V  (AOFS_K + 2*64*KSS)
#define AOFS_PQ (AOFS_V + 2*64*VSS)
#define AOFS_PK (AOFS_PQ + 192)
#define AOFS_RS (AOFS_PK + 384)
#define AOFS_RT (AOFS_RS + 256)
#define ATT_FLOATS (AOFS_RT + 64)

__global__ __launch_bounds__(512, 2)
void attn_kernel(const float* __restrict__ pos, const float* __restrict__ qkv,
                 float* __restrict__ upd) {
    extern __shared__ float sm[];
    float* Qs  = sm;
    float* P   = sm + AOFS_P;
    float* Kb  = sm + AOFS_K;
    float* Vb  = sm + AOFS_V;
    float* pq  = sm + AOFS_PQ;
    float* pk  = sm + AOFS_PK;
    float* rsP = sm + AOFS_RS;
    float* rsum= sm + AOFS_RT;

    const int t = threadIdx.x;
    const int w = t >> 5, l = t & 31, g = l >> 2, ti = l & 3;
    const int wm = w >> 2, wn = w & 3;
    const int qt = blockIdx.x, h = blockIdx.y, b = blockIdx.z;
    const int q0g = qt * 64, tokbase = b * SEQ;

    #pragma unroll
    for (int i = t; i < 64 * 16; i += 512) {
        int q = i >> 4, d4 = (i & 15) * 4;
        cp16(&Qs[q*QSS + d4], &qkv[(size_t)(tokbase + q0g + q)*1536 + h*64 + d4]);
    }
    #pragma unroll
    for (int i = t; i < 64 * 16; i += 512) {
        int k = i >> 4, d4 = (i & 15) * 4;
        cp16(&Kb[k*KSS + d4], &qkv[(size_t)(tokbase + k)*1536 + 512 + h*64 + d4]);
    }
    #pragma unroll
    for (int i = t; i < 64 * 16; i += 512) {
        int k = i >> 4, d4 = (i & 15) * 4;
        cp16(&Vb[k*VSS + d4], &qkv[(size_t)(tokbase + k)*1536 + 1024 + h*64 + d4]);
    }
    if (t < 192) cp4(&pq[t], &pos[(size_t)(tokbase + q0g)*3 + t]);
    else if (t < 384) cp4(&pk[t-192], &pos[(size_t)tokbase*3 + (t-192)]);
    CP_COMMIT();

    const float K1 = (float)(1.4426950408889634 * 0.08838834764831845);
    const float C2 = (float)(1.4142135623730951 * 1.4426950408889634);
    float cO[2][4] = {};
    float rs0 = 0.f, rs1 = 0.f;

    for (int c = 0; c < 8; c++) {
        CP_WAIT0();
        __syncthreads();
        if (c < 7) {
            const int nx = (c + 1) & 1;
            #pragma unroll
            for (int i = t; i < 64 * 16; i += 512) {
                int k = i >> 4, d4 = (i & 15) * 4;
                cp16(&Kb[nx*64*KSS + k*KSS + d4],
                     &qkv[(size_t)(tokbase + (c+1)*64 + k)*1536 + 512 + h*64 + d4]);
            }
            #pragma unroll
            for (int i = t; i < 64 * 16; i += 512) {
                int k = i >> 4, d4 = (i & 15) * 4;
                cp16(&Vb[nx*64*VSS + k*VSS + d4],
                     &qkv[(size_t)(tokbase + (c+1)*64 + k)*1536 + 1024 + h*64 + d4]);
            }
            if (t < 192) cp4(&pk[nx*192 + t], &pos[(size_t)(tokbase + (c+1)*64)*3 + t]);
            CP_COMMIT();
        }
        const float* Kc = Kb + (c & 1) * 64 * KSS;

        float cS[2][4] = {};
        #pragma unroll
        for (int ks = 0; ks < 8; ks++) {
            float a[4], bf[2][2];
            a[0] = Qs[(wm*16 + g)     * QSS + ks*8 + ti];
            a[1] = Qs[(wm*16 + g + 8) * QSS + ks*8 + ti];
            a[2] = Qs[(wm*16 + g)     * QSS + ks*8 + ti + 4];
            a[3] = Qs[(wm*16 + g + 8) * QSS + ks*8 + ti + 4];
            #pragma unroll
            for (int nt = 0; nt < 2; nt++) {
                int key = wn*16 + nt*8 + g;
                bf[nt][0] = Kc[key*KSS + ks*8 + ti];
                bf[nt][1] = Kc[key*KSS + ks*8 + ti + 4];
            }
            mma8(cS[0], a, bf[0]);
            mma8(cS[1], a, bf[1]);
        }

        {
            const int r0 = wm*16 + g;
            const float qx0 = pq[r0*3],     qy0 = pq[r0*3+1],     qz0 = pq[r0*3+2];
            const float qx1 = pq[(r0+8)*3], qy1 = pq[(r0+8)*3+1], qz1 = pq[(r0+8)*3+2];
            const float* pkc = pk + (c & 1) * 192;
            #pragma unroll
            for (int nt = 0; nt < 2; nt++) {
                int kl = wn*16 + nt*8 + 2*ti;
                float kx0 = pkc[kl*3],   ky0 = pkc[kl*3+1], kz0 = pkc[kl*3+2];
                float kx1 = pkc[kl*3+3], ky1 = pkc[kl*3+4], kz1 = pkc[kl*3+5];
                float dx, dy, dz;
                dx = qx0-kx0; dy = qy0-ky0; dz = qz0-kz0;
                float e00 = fsqrt_fast(fmaf(dx,dx,fmaf(dy,dy,dz*dz))) * C2;
                dx = qx0-kx1; dy = qy0-ky1; dz = qz0-kz1;
                float e01 = fsqrt_fast(fmaf(dx,dx,fmaf(dy,dy,dz*dz))) * C2;
                dx = qx1-kx0; dy = qy1-ky0; dz = qz1-kz0;
                float e10 = fsqrt_fast(fmaf(dx,dx,fmaf(dy,dy,dz*dz))) * C2;
                dx = qx1-kx1; dy = qy1-ky1; dz = qz1-kz1;
                float e11 = fsqrt_fast(fmaf(dx,dx,fmaf(dy,dy,dz*dz))) * C2;
                float2 u0, u1;
                u0.x = totf32(exp2_fast(fmaf(cS[nt][0], K1, e00)));
                u0.y = totf32(exp2_fast(fmaf(cS[nt][1], K1, e01)));
                u1.x = totf32(exp2_fast(fmaf(cS[nt][2], K1, e10)));
                u1.y = totf32(exp2_fast(fmaf(cS[nt][3], K1, e11)));
                *(float2*)&P[r0*PSS + kl]     = u0;
                *(float2*)&P[(r0+8)*PSS + kl] = u1;
                rs0 += u0.x + u0.y;
                rs1 += u1.x + u1.y;
            }
        }
        __syncthreads();

        const float* Vc = Vb + (c & 1) * 64 * VSS;
        #pragma unroll
        for (int ks = 0; ks < 8; ks++) {
            float a[4], bf[2][2];
            a[0] = P[(wm*16 + g)     * PSS + ks*8 + ti];
            a[1] = P[(wm*16 + g + 8) * PSS + ks*8 + ti];
            a[2] = P[(wm*16 + g)     * PSS + ks*8 + ti + 4];
            a[3] = P[(wm*16 + g + 8) * PSS + ks*8 + ti + 4];
            #pragma unroll
            for (int nt = 0; nt < 2; nt++) {
                int dc = wn*16 + nt*8 + g;
                bf[nt][0] = Vc[(ks*8 + ti)     * VSS + dc];
                bf[nt][1] = Vc[(ks*8 + ti + 4) * VSS + dc];
            }
            mma8(cO[0], a, bf[0]);
            mma8(cO[1], a, bf[1]);
        }
    }

    rs0 += __shfl_xor_sync(0xffffffffu, rs0, 1);
    rs0 += __shfl_xor_sync(0xffffffffu, rs0, 2);
    rs1 += __shfl_xor_sync(0xffffffffu, rs1, 1);
    rs1 += __shfl_xor_sync(0xffffffffu, rs1, 2);
    __syncthreads();
    if (ti == 0) {
        rsP[wn*64 + wm*16 + g]     = rs0;
        rsP[wn*64 + wm*16 + g + 8] = rs1;
    }
    __syncthreads();
    if (t < 64) rsum[t] = 1.f / (rsP[t] + rsP[64 + t] + rsP[128 + t] + rsP[192 + t]);
    __syncthreads();

    {
        float inv0 = rsum[wm*16 + g];
        float inv1 = rsum[wm*16 + g + 8];
        #pragma unroll
        for (int nt = 0; nt < 2; nt++) {
            int r = tokbase + q0g + wm*16 + g;
            int col = h*64 + wn*16 + nt*8 + 2*ti;
            *(float2*)&upd[(size_t)r * HDIM + col] =
                make_float2(totf32(cO[nt][0]*inv0), totf32(cO[nt][1]*inv0));
            *(float2*)&upd[(size_t)(r + 8) * HDIM + col] =
                make_float2(totf32(cO[nt][2]*inv1), totf32(cO[nt][3]*inv1));
        }
    }
}

// ---- fused 3-layer MLP (r13-proven configuration) ----
#define MH1S 132
#define MH2S 68
#define MAS  36
#define MBS  136
#define MW2S 72
#define MW3S 264
#define MOFS_H2 (128*MH1S)
#define MOFS_ST (MOFS_H2 + 128*MH2S)
#define MOFS_BS (MOFS_ST + 128*MAS)
#define MOFS_W2 (MOFS_ST + 64*MW3S)
#define MLP_FLOATS (MOFS_W2 + 128*MW2S)

__global__ __launch_bounds__(512, 1)
void mlp_fused(const float* __restrict__ X,
               const float* __restrict__ W1, const float* __restrict__ b1,
               const float* __restrict__ W2, const float* __restrict__ b2,
               const float* __restrict__ W3, const float* __restrict__ b3,
               float* __restrict__ out) {
    extern __shared__ float sm[];
    float* H1  = sm;
    float* H2  = sm + MOFS_H2;
    float* As  = sm + MOFS_ST;
    float* Bs  = sm + MOFS_BS;
    float* W3s = sm + MOFS_ST;
    float* W2s = sm + MOFS_W2;

    const int t = threadIdx.x;
    const int w = t >> 5, l = t & 31, g = l >> 2, ti = l & 3;
    const int wm = w >> 2, wn = w & 3;
    const int bm = blockIdx.x * 128;

    #pragma unroll
    for (int j = 0; j < 4; j++) {
        int i = t + 512*j; int kr = i >> 4, n4 = (i & 15) * 4;
        cp16(&W2s[kr*MW2S + n4], &W2[kr*64 + n4]);
    }
    CP_COMMIT();

    const float* A = X + (size_t)bm * HDIM;
    float4 ra[2], rb[2];
    #pragma unroll
    for (int j = 0; j < 2; j++) { int i = t + 512*j;
        ra[j] = *(const float4*)&A[(size_t)(i>>3) * HDIM + (i&7)*4]; }
    #pragma unroll
    for (int j = 0; j < 2; j++) { int i = t + 512*j;
        rb[j] = *(const float4*)&W1[(size_t)(i>>5) * 128 + (i&31)*4]; }

    float c1[2][4][4] = {};
    for (int kt = 0; kt < HDIM; kt += 32) {
        #pragma unroll
        for (int j = 0; j < 2; j++) { int i = t + 512*j;
            *(float4*)&As[(i>>3)*MAS + (i&7)*4] = ra[j]; }
        #pragma unroll
        for (int j = 0; j < 2; j++) { int i = t + 512*j;
            *(float4*)&Bs[(i>>5)*MBS + (i&31)*4] = cvt4(rb[j]); }
        __syncthreads();
        if (kt + 32 < HDIM) {
            #pragma unroll
            for (int j = 0; j < 2; j++) { int i = t + 512*j;
                ra[j] = *(const float4*)&A[(size_t)(i>>3) * HDIM + kt + 32 + (i&7)*4]; }
            #pragma unroll
            for (int j = 0; j < 2; j++) { int i = t + 512*j;
                rb[j] = *(const float4*)&W1[(size_t)(kt + 32 + (i>>5)) * 128 + (i&31)*4]; }
        }
        #pragma unroll
        for (int ks = 0; ks < 4; ks++) {
            float a[2][4], bfr[4][2];
            #pragma unroll
            for (int mt = 0; mt < 2; mt++) {
                int r = wm*32 + mt*16;
                a[mt][0] = As[(r + g)     * MAS + ks*8 + ti];
                a[mt][1] = As[(r + g + 8) * MAS + ks*8 + ti];
                a[mt][2] = As[(r + g)     * MAS + ks*8 + ti + 4];
                a[mt][3] = As[(r + g + 8) * MAS + ks*8 + ti + 4];
            }
            #pragma unroll
            for (int nt = 0; nt < 4; nt++) {
                int cc = wn*32 + nt*8 + g;
                bfr[nt][0] = Bs[(ks*8 + ti)     * MBS + cc];
                bfr[nt][1] = Bs[(ks*8 + ti + 4) * MBS + cc];
            }
            #pragma unroll
            for (int mt = 0; mt < 2; mt++)
                #pragma unroll
                for (int nt = 0; nt < 4; nt++)
                    mma8(c1[mt][nt], a[mt], bfr[nt]);
        }
        __syncthreads();
    }
    #pragma unroll
    for (int mt = 0; mt < 2; mt++)
        #pragma unroll
        for (int nt = 0; nt < 4; nt++) {
            int row = wm*32 + mt*16 + g;
            int col = wn*32 + nt*8 + 2*ti;
            float bb0 = b1[col], bb1 = b1[col+1];
            float v0 = c1[mt][nt][0] + bb0, v1 = c1[mt][nt][1] + bb1;
            float v2 = c1[mt][nt][2] + bb0, v3 = c1[mt][nt][3] + bb1;
            v0 = totf32(v0 / (1.f + __expf(-v0))); v1 = totf32(v1 / (1.f + __expf(-v1)));
            v2 = totf32(v2 / (1.f + __expf(-v2))); v3 = totf32(v3 / (1.f + __expf(-v3)));
            *(float2*)&H1[row*MH1S + col]     = make_float2(v0, v1);
            *(float2*)&H1[(row+8)*MH1S + col] = make_float2(v2, v3);
        }
    __syncthreads();

    #pragma unroll
    for (int j = 0; j < 8; j++) {
        int i = t + 512*j; int kr = i >> 6, n4 = (i & 63) * 4;
        cp16(&W3s[kr*MW3S + n4], &W3[kr*256 + n4]);
    }
    CP_COMMIT();
    CP_WAIT1();
    __syncthreads();

    float c2[2][2][4] = {};
    #pragma unroll
    for (int ks = 0; ks < 16; ks++) {
        float a[2][4], bfr[2][2];
        #pragma unroll
        for (int mt = 0; mt < 2; mt++) {
            int r = wm*32 + mt*16;
            a[mt][0] = H1[(r + g)     * MH1S + ks*8 + ti];
            a[mt][1] = H1[(r + g + 8) * MH1S + ks*8 + ti];
            a[mt][2] = H1[(r + g)     * MH1S + ks*8 + ti + 4];
            a[mt][3] = H1[(r + g + 8) * MH1S + ks*8 + ti + 4];
        }
        #pragma unroll
        for (int nt = 0; nt < 2; nt++) {
            int cc = wn*16 + nt*8 + g;
            bfr[nt][0] = totf32(W2s[(ks*8 + ti)     * MW2S + cc]);
            bfr[nt][1] = totf32(W2s[(ks*8 + ti + 4) * MW2S + cc]);
        }
        #pragma unroll
        for (int mt = 0; mt < 2; mt++)
            #pragma unroll
            for (int nt = 0; nt < 2; nt++)
                mma8(c2[mt][nt], a[mt], bfr[nt]);
    }
    #pragma unroll
    for (int mt = 0; mt < 2; mt++)
        #pragma unroll
        for (int nt = 0; nt < 2; nt++) {
            int row = wm*32 + mt*16 + g;
            int col = wn*16 + nt*8 + 2*ti;
            float bb0 = b2[col], bb1 = b2[col+1];
            float v0 = c2[mt][nt][0] + bb0, v1 = c2[mt][nt][1] + bb1;
            float v2 = c2[mt][nt][2] + bb0, v3 = c2[mt][nt][3] + bb1;
            v0 = totf32(v0 / (1.f + __expf(-v0))); v1 = totf32(v1 / (1.f + __expf(-v1)));
            v2 = totf32(v2 / (1.f + __expf(-v2))); v3 = totf32(v3 / (1.f + __expf(-v3)));
            *(float2*)&H2[row*MH2S + col]     = make_float2(v0, v1);
            *(float2*)&H2[(row+8)*MH2S + col] = make_float2(v2, v3);
        }
    CP_WAIT0();
    __syncthreads();

    float c3[2][8][4] = {};
    #pragma unroll
    for (int ks = 0; ks < 8; ks++) {
        float a[2][4];
        #pragma unroll
        for (int mt = 0; mt < 2; mt++) {
            int r = wm*32 + mt*16;
            a[mt][0] = H2[(r + g)     * MH2S + ks*8 + ti];
            a[mt][1] = H2[(r + g + 8) * MH2S + ks*8 + ti];
            a[mt][2] = H2[(r + g)     * MH2S + ks*8 + ti + 4];
            a[mt][3] = H2[(r + g + 8) * MH2S + ks*8 + ti + 4];
        }
        #pragma unroll
        for (int nt = 0; nt < 8; nt++) {
            float bfr[2];
            int cc = wn*64 + nt*8 + g;
            bfr[0] = totf32(W3s[(ks*8 + ti)     * MW3S + cc]);
            bfr[1] = totf32(W3s[(ks*8 + ti + 4) * MW3S + cc]);
            mma8(c3[0][nt], a[0], bfr);
            mma8(c3[1][nt], a[1], bfr);
        }
    }
    #pragma unroll
    for (int mt = 0; mt < 2; mt++)
        #pragma unroll
        for (int nt = 0; nt < 8; nt++) {
            int row = bm + wm*32 + mt*16 + g;
            int col = wn*64 + nt*8 + 2*ti;
            float bb0 = b3[col], bb1 = b3[col+1];
            float v0 = c3[mt][nt][0] + bb0, v1 = c3[mt][nt][1] + bb1;
            float v2 = c3[mt][nt][2] + bb0, v3 = c3[mt][nt][3] + bb1;
            v0 = v0 / (1.f + __expf(-v0)); v1 = v1 / (1.f + __expf(-v1));
            v2 = v2 / (1.f + __expf(-v2)); v3 = v3 / (1.f + __expf(-v3));
            *(float2*)&out[(size_t)row * INDIM + col]     = make_float2(v0, v1);
            *(float2*)&out[(size_t)(row+8) * INDIM + col] = make_float2(v2, v3);
        }
}

// ---- launch ----
extern "C" void kernel_launch(void* const* d_in, const int* in_sizes, int n_in,
                              void* d_out, int out_size) {
    const float* pos  = (const float*)d_in[0];
    const float* feat = (const float*)d_in[1];
    const float* Wk   = (const float*)d_in[2];
    const float* Wq   = (const float*)d_in[3];
    const float* Wv   = (const float*)d_in[4];
    const float* W1   = (const float*)d_in[5];
    const float* b1   = (const float*)d_in[6];
    const float* W2   = (const float*)d_in[7];
    const float* b2   = (const float*)d_in[8];
    const float* W3   = (const float*)d_in[9];
    const float* b3   = (const float*)d_in[10];
    float* out = (float*)d_out;

    void* p;
    cudaGetSymbolAddress(&p, g_qkv);   float* qkv   = (float*)p;
    cudaGetSymbolAddress(&p, g_upd);   float* upd   = (float*)p;
    cudaGetSymbolAddress(&p, g_featr); float* featr = (float*)p;
    cudaGetSymbolAddress(&p, g_wcat);  float* wcat  = (float*)p;

    prep_round<<<(MTOK*INDIM/4 + INDIM*1536/4 + 255)/256, 256>>>(feat, Wq, Wk, Wv, featr, wcat);

    size_t gsh = (size_t)GEMM_FLOATS * sizeof(float);
    cudaFuncSetAttribute(qkv_gemm2, cudaFuncAttributeMaxDynamicSharedMemorySize, (int)gsh);
    qkv_gemm2<<<dim3(12, MTOK/128), 256, gsh>>>(featr, wcat, qkv);

    size_t ash = (size_t)ATT_FLOATS * sizeof(float);
    cudaFuncSetAttribute(attn_kernel, cudaFuncAttributeMaxDynamicSharedMemorySize, (int)ash);
    attn_kernel<<<dim3(SEQ/64, NHEADS, BATCH), 512, ash>>>(pos, qkv, upd);

    size_t msh = (size_t)MLP_FLOATS * sizeof(float);
    cudaFuncSetAttribute(mlp_fused, cudaFuncAttributeMaxDynamicSharedMemorySize, (int)msh);
    mlp_fused<<<MTOK/128, 512, msh>>>(upd, W1, b1, W2, b2, W3, b3, out);
}